// round 14
// baseline (speedup 1.0000x reference)
#include <cuda_runtime.h>
#include <cuda_bf16.h>

// Problem constants
// B=4, N=2048, D=1024, H=16, HD=64, N_SCALES=11, N_TAPS=4
// M = B*N = 8192 rows.

// ---------------- scratch (device globals; no allocation allowed) ----------
__device__ float g_qkv [8192 * 3072];   // qkv projection output [M, 3D]
__device__ float g_gate[8192 * 1024];   // sigmoid gate          [M, D]
__device__ float g_G   [8192 * 1024];   // gated gathered attn   [M, D]

// ---------------- helpers --------------------------------------------------
__device__ __forceinline__ float warp_sum(float v) {
#pragma unroll
    for (int s = 16; s > 0; s >>= 1) v += __shfl_xor_sync(0xffffffffu, v, s);
    return v;
}

// ---------------- fp32 NT GEMM: C[m,n] = act( sum_k A[m,k]*B[n,k] + bias[n] )
// A: [M,K] row-major, B: [N,K] row-major (i.e. A @ B^T). 128x128 tile, BK=8,
// 256 threads, 8x8 per thread. All dims are multiples of 128/8 here.
__global__ void __launch_bounds__(256) gemm_nt(
    const float* __restrict__ A, const float* __restrict__ B,
    const float* __restrict__ bias, float* __restrict__ C,
    int M, int N, int K, int act)
{
    __shared__ __align__(16) float As[8][128];
    __shared__ __align__(16) float Bs[8][128];

    const int tid  = threadIdx.x;
    const int m0   = blockIdx.y * 128;
    const int n0   = blockIdx.x * 128;
    const int lrow = tid >> 1;          // 0..127
    const int lcol = (tid & 1) << 2;    // 0 or 4
    const float* Ap = A + (size_t)(m0 + lrow) * K + lcol;
    const float* Bp = B + (size_t)(n0 + lrow) * K + lcol;
    const int ty = tid >> 4;            // 0..15
    const int tx = tid & 15;            // 0..15

    float acc[8][8];
#pragma unroll
    for (int i = 0; i < 8; i++)
#pragma unroll
        for (int j = 0; j < 8; j++) acc[i][j] = 0.f;

    for (int k0 = 0; k0 < K; k0 += 8) {
        float4 av = *(const float4*)(Ap + k0);
        float4 bv = *(const float4*)(Bp + k0);
        __syncthreads();
        As[lcol + 0][lrow] = av.x; As[lcol + 1][lrow] = av.y;
        As[lcol + 2][lrow] = av.z; As[lcol + 3][lrow] = av.w;
        Bs[lcol + 0][lrow] = bv.x; Bs[lcol + 1][lrow] = bv.y;
        Bs[lcol + 2][lrow] = bv.z; Bs[lcol + 3][lrow] = bv.w;
        __syncthreads();
#pragma unroll
        for (int kk = 0; kk < 8; kk++) {
            float4 a0 = *(const float4*)&As[kk][ty * 8];
            float4 a1 = *(const float4*)&As[kk][ty * 8 + 4];
            float4 b0 = *(const float4*)&Bs[kk][tx * 8];
            float4 b1 = *(const float4*)&Bs[kk][tx * 8 + 4];
            float a[8] = {a0.x, a0.y, a0.z, a0.w, a1.x, a1.y, a1.z, a1.w};
            float b[8] = {b0.x, b0.y, b0.z, b0.w, b1.x, b1.y, b1.z, b1.w};
#pragma unroll
            for (int i = 0; i < 8; i++)
#pragma unroll
                for (int j = 0; j < 8; j++)
                    acc[i][j] = fmaf(a[i], b[j], acc[i][j]);
        }
    }

    const int cn = n0 + tx * 8;
    float bvals[8];
#pragma unroll
    for (int j = 0; j < 8; j++) bvals[j] = bias[cn + j];
#pragma unroll
    for (int i = 0; i < 8; i++) {
        float out[8];
#pragma unroll
        for (int j = 0; j < 8; j++) {
            float v = acc[i][j] + bvals[j];
            if (act == 1) v = 1.f / (1.f + __expf(-v));  // sigmoid
            out[j] = v;
        }
        float* Crow = C + (size_t)(m0 + ty * 8 + i) * N + cn;
        *(float4*)(Crow)     = make_float4(out[0], out[1], out[2], out[3]);
        *(float4*)(Crow + 4) = make_float4(out[4], out[5], out[6], out[7]);
    }
}

// ---------------- DWARF attention core ------------------------------------
// One warp per (b,h,n); lanes split the 64-dim head (2 floats per lane).
// 22 distinct tap offsets (offset 0 carries 11 taps + bypass; even-index
// offsets 2*2^m carry two (j,tau) pairs). Important: when n-offset<0 the
// v term vanishes but z STILL accumulates elu(bias)+1 per the reference.
__global__ void __launch_bounds__(256) attn_kernel(
    const float* __restrict__ qkv, const float* __restrict__ gate,
    const float* __restrict__ Wqs, const float* __restrict__ sg,
    const float* __restrict__ idb, const float* __restrict__ pb,
    float* __restrict__ G)
{
    const int lane = threadIdx.x & 31;
    const int wid  = (blockIdx.x << 3) + (threadIdx.x >> 5); // 131072 warps
    const int n = wid & 2047;
    const int h = (wid >> 11) & 15;
    const int b = wid >> 15;

    const float2 q2 = *(const float2*)(qkv + ((size_t)(b * 2048 + n)) * 3072 + h * 64 + 2 * lane);

    // ---- gains = softmax_s( q . W_qscale[s] + scale_gain[s,h] ) ----
    float gains[11];
    float mx = -1e30f;
#pragma unroll
    for (int s = 0; s < 11; s++) {
        float2 w = *(const float2*)(Wqs + s * 64 + 2 * lane);
        float p = warp_sum(q2.x * w.x + q2.y * w.y) + sg[s * 16 + h];
        gains[s] = p;
        mx = fmaxf(mx, p);
    }
    float ssum = 0.f;
#pragma unroll
    for (int s = 0; s < 11; s++) { float e = __expf(gains[s] - mx); gains[s] = e; ssum += e; }
    {
        float inv = 1.f / ssum;
#pragma unroll
        for (int s = 0; s < 11; s++) gains[s] *= inv;
    }

    const float* kb = qkv + ((size_t)b * 2048) * 3072 + 1024 + h * 64 + 2 * lane;
    const float* vb = kb + 1024;

    const float D4v[4] = {0.4829629131445341f, 0.8365163037378079f,
                          0.2241438680420134f, -0.1294095225512604f};

    // ---- offset-0: 11 tau=0 taps + identity bypass share dot(q,k[n]) ----
    const float2 k0 = *(const float2*)(kb + (size_t)n * 3072);
    const float2 v0 = *(const float2*)(vb + (size_t)n * 3072);
    const float dot0 = warp_sum(q2.x * k0.x + q2.y * k0.y);

    float ax = 0.f, ay = 0.f, z = 0.f;
#pragma unroll
    for (int j = 0; j < 11; j++) {
        float t = dot0 + pb[(j * 4) * 16 + h];
        float feat = (t > 0.f) ? (t + 1.f) : __expf(t);      // elu(t)+1
        float w = gains[j] * D4v[0] * feat;                  // D4[0] > 0
        ax = fmaf(w, v0.x, ax); ay = fmaf(w, v0.y, ay); z += w;
    }
    {
        float byp = log1pf(__expf(idb[h]));                  // softplus
        float lf  = (dot0 > 0.f) ? (dot0 + 1.f) : __expf(dot0);
        float w = byp * lf;
        ax = fmaf(w, v0.x, ax); ay = fmaf(w, v0.y, ay); z += w;
    }

    // ---- 21 nonzero distinct offsets ----
    // odd index i => offset 2*2^m carries pairs (J1[i], T1[i]) and (J1[i]+1, 1)
    const int OFF[21] = {1,2,3,4,6,8,12,16,24,32,48,64,96,128,192,256,384,512,768,1024,1536};
    const int J1 [21] = {0,0,0,1,1,2,2,3,3,4,4,5,5,6,6,7,7,8,8,9,9};
    const int T1 [21] = {1,2,3,2,3,2,3,2,3,2,3,2,3,2,3,2,3,2,3,2,3};

#pragma unroll
    for (int i = 0; i < 21; i++) {
        const int m = n - OFF[i];
        float dpart = 0.f;
        float2 vm = make_float2(0.f, 0.f);
        if (m >= 0) {   // warp-uniform branch
            float2 km = *(const float2*)(kb + (size_t)m * 3072);
            vm        = *(const float2*)(vb + (size_t)m * 3072);
            dpart = q2.x * km.x + q2.y * km.y;
        }
        const float dot = warp_sum(dpart);                   // 0 when m<0

        const int j1 = J1[i], tt = T1[i];
        float t    = dot + pb[(j1 * 4 + tt) * 16 + h];
        float feat = (t > 0.f) ? (t + 1.f) : __expf(t);
        float c1   = D4v[tt];
        float w    = gains[j1] * c1 * feat;
        float zc   = gains[j1] * fabsf(c1) * feat;
        if (i & 1) {  // second pair (j1+1, tau=1), D4[1] > 0
            float t2 = dot + pb[((j1 + 1) * 4 + 1) * 16 + h];
            float f2 = (t2 > 0.f) ? (t2 + 1.f) : __expf(t2);
            float w2 = gains[j1 + 1] * D4v[1] * f2;
            w += w2; zc += w2;
        }
        z += zc;                                             // always (bias-only when m<0)
        if (m >= 0) { ax = fmaf(w, vm.x, ax); ay = fmaf(w, vm.y, ay); }
    }

    // ---- normalize, gate, scatter to [B,N,D] ----
    const float invz = 1.f / (z + 1e-6f);
    const size_t gi = (size_t)(b * 2048 + n) * 1024 + h * 64 + 2 * lane;
    const float2 gt = *(const float2*)(gate + gi);
    float2 o;
    o.x = ax * invz * gt.x;
    o.y = ay * invz * gt.y;
    *(float2*)(G + gi) = o;
}

// ---------------- launch ---------------------------------------------------
extern "C" void kernel_launch(void* const* d_in, const int* in_sizes, int n_in,
                              void* d_out, int out_size) {
    const float* x    = (const float*)d_in[0];
    const float* Wqkv = (const float*)d_in[1];
    const float* bqkv = (const float*)d_in[2];
    const float* Wout = (const float*)d_in[3];
    const float* bout = (const float*)d_in[4];
    const float* Wg   = (const float*)d_in[5];
    const float* bg   = (const float*)d_in[6];
    const float* sg   = (const float*)d_in[7];
    const float* Wqs  = (const float*)d_in[8];
    const float* idb  = (const float*)d_in[9];
    const float* pb   = (const float*)d_in[10];
    float* out = (float*)d_out;

    float *qkv, *gate, *G;
    cudaGetSymbolAddress((void**)&qkv,  g_qkv);
    cudaGetSymbolAddress((void**)&gate, g_gate);
    cudaGetSymbolAddress((void**)&G,    g_G);

    dim3 blk(256);
    // 1) qkv = x @ W_qkv^T + b_qkv             [8192, 3072]
    gemm_nt<<<dim3(3072 / 128, 8192 / 128), blk>>>(x, Wqkv, bqkv, qkv, 8192, 3072, 1024, 0);
    // 2) gate = sigmoid(x @ W_gate^T + b_gate) [8192, 1024]
    gemm_nt<<<dim3(1024 / 128, 8192 / 128), blk>>>(x, Wg, bg, gate, 8192, 1024, 1024, 1);
    // 3) DWARF attention -> gated gathered G   [8192, 1024]
    attn_kernel<<<131072 / 8, 256>>>(qkv, gate, Wqs, sg, idb, pb, G);
    // 4) out = G @ W_out^T + b_out             [8192, 1024]
    gemm_nt<<<dim3(1024 / 128, 8192 / 128), blk>>>(G, Wout, bout, out, 8192, 1024, 1024, 0);
}

// round 16
// speedup vs baseline: 2.3060x; 2.3060x over previous
#include <cuda_runtime.h>
#include <cuda_bf16.h>
#include <cstdint>

// Problem constants: B=4, N=2048, D=1024, H=16, HD=64, M=B*N=8192, K=1024 everywhere.

// ---------------- scratch (device globals; no allocation allowed) ----------
__device__ float g_qkv [8192u * 3072u];          // qkv projection output (fp32)
__device__ float g_gate[8192u * 1024u];          // sigmoid gate (fp32)
__device__ __nv_bfloat16 g_xh [8192u * 1024u];   // x hi/lo
__device__ __nv_bfloat16 g_xl [8192u * 1024u];
__device__ __nv_bfloat16 g_Wqh[3072u * 1024u];   // W_qkv hi/lo
__device__ __nv_bfloat16 g_Wql[3072u * 1024u];
__device__ __nv_bfloat16 g_Wgh[1024u * 1024u];   // W_gate hi/lo
__device__ __nv_bfloat16 g_Wgl[1024u * 1024u];
__device__ __nv_bfloat16 g_Woh[1024u * 1024u];   // W_out hi/lo
__device__ __nv_bfloat16 g_Wol[1024u * 1024u];
__device__ __nv_bfloat16 g_Gh [8192u * 1024u];   // gated attn output hi/lo
__device__ __nv_bfloat16 g_Gl [8192u * 1024u];

// ---------------- helpers ---------------------------------------------------
__device__ __forceinline__ uint32_t smem_u32(const void* p) {
    return (uint32_t)__cvta_generic_to_shared(p);
}
__device__ __forceinline__ float warp_sum(float v) {
#pragma unroll
    for (int s = 16; s > 0; s >>= 1) v += __shfl_xor_sync(0xffffffffu, v, s);
    return v;
}
__device__ __forceinline__ void ldsm4(uint32_t* r, uint32_t addr) {
    asm volatile("ldmatrix.sync.aligned.m8n8.x4.shared.b16 {%0,%1,%2,%3}, [%4];"
                 : "=r"(r[0]), "=r"(r[1]), "=r"(r[2]), "=r"(r[3]) : "r"(addr));
}
__device__ __forceinline__ void mma_bf16(float* c, const uint32_t* a, const uint32_t* b) {
    asm volatile(
        "mma.sync.aligned.m16n8k16.row.col.f32.bf16.bf16.f32 "
        "{%0,%1,%2,%3}, {%4,%5,%6,%7}, {%8,%9}, {%0,%1,%2,%3};"
        : "+f"(c[0]), "+f"(c[1]), "+f"(c[2]), "+f"(c[3])
        : "r"(a[0]), "r"(a[1]), "r"(a[2]), "r"(a[3]), "r"(b[0]), "r"(b[1]));
}

// ---------------- fp32 -> (hi, lo) bf16 split -------------------------------
__global__ void __launch_bounds__(256) split_hl(
    const float* __restrict__ src, __nv_bfloat16* __restrict__ hi,
    __nv_bfloat16* __restrict__ lo, int n2)
{
    int i = blockIdx.x * 256 + threadIdx.x;
    if (i >= n2) return;
    float2 v = ((const float2*)src)[i];
    __nv_bfloat16 hx = __float2bfloat16(v.x);
    __nv_bfloat16 hy = __float2bfloat16(v.y);
    __nv_bfloat162 h2; h2.x = hx; h2.y = hy;
    __nv_bfloat162 l2;
    l2.x = __float2bfloat16(v.x - __bfloat162float(hx));
    l2.y = __float2bfloat16(v.y - __bfloat162float(hy));
    ((__nv_bfloat162*)hi)[i] = h2;
    ((__nv_bfloat162*)lo)[i] = l2;
}

// ---------------- cp.async loader: 128x64 bf16 tile, SW128 swizzle ----------
// K is fixed at 1024 elements for all GEMMs. 128 rows x 128 bytes per tile.
__device__ __forceinline__ void load_tile(uint32_t dst,
                                          const __nv_bfloat16* __restrict__ g,
                                          int row0, int k0, int tid)
{
    const __nv_bfloat16* base = g + (size_t)row0 * 1024 + k0;
#pragma unroll
    for (int it = 0; it < 4; ++it) {
        int s = tid + it * 256;                  // 1024 x 16B segments
        int r = s >> 3, sc = s & 7;
        uint32_t off = (uint32_t)(r * 128 + sc * 16);
        uint32_t d = dst + (off ^ ((off >> 3) & 0x70u));
        const void* src = base + (size_t)r * 1024 + sc * 8;
        asm volatile("cp.async.cg.shared.global [%0], [%1], 16;" :: "r"(d), "l"(src));
    }
}

// ---------------- HMMA bf16-split NT GEMM -----------------------------------
// C[m,n] = act( sum_k A[m,k]*B[n,k] + bias[n] ), A=Ah+Al, B=Bh+Bl (bf16),
// products Ah*Bh + Ah*Bl + Al*Bh, fp32 register accumulation.
// CTA tile 128x128, BK=64, 8 warps (2x4), warp tile 64x32, 2-stage cp.async.
#define GEMM_SMEM (1024u + 131072u)

__global__ void __launch_bounds__(256, 1) gemm_tc(
    const __nv_bfloat16* __restrict__ Ahp, const __nv_bfloat16* __restrict__ Alp,
    const __nv_bfloat16* __restrict__ Bhp, const __nv_bfloat16* __restrict__ Blp,
    const float* __restrict__ bias, float* __restrict__ C,
    int N, int act)
{
    extern __shared__ char dsm[];
    const int tid  = threadIdx.x;
    const int lane = tid & 31;
    const int wid  = tid >> 5;
    const int warpM = wid >> 2;            // 0..1
    const int warpN = wid & 3;             // 0..3
    const int m0 = blockIdx.y * 128;
    const int n0 = blockIdx.x * 128;
    const uint32_t sb = (smem_u32(dsm) + 1023u) & ~1023u;

    float acc[4][4][4];
#pragma unroll
    for (int a = 0; a < 4; a++)
#pragma unroll
        for (int b = 0; b < 4; b++)
#pragma unroll
            for (int c = 0; c < 4; c++) acc[a][b][c] = 0.f;

    // prologue: stage 0 <- chunk 0
    load_tile(sb + 0u,      Ahp, m0, 0, tid);
    load_tile(sb + 16384u,  Alp, m0, 0, tid);
    load_tile(sb + 32768u,  Bhp, n0, 0, tid);
    load_tile(sb + 49152u,  Blp, n0, 0, tid);
    asm volatile("cp.async.commit_group;");

    // ldmatrix addressing: rows have 128B stride; SW128 XOR mask = (row&7)<<4.
    const uint32_t rmask   = (uint32_t)((lane & 7) << 4);
    const uint32_t halfoff = (uint32_t)((lane >> 4) << 4);   // k-half select
    const uint32_t baseA = (uint32_t)((warpM * 64 + (lane & 15)) * 128);
    const uint32_t baseB = (uint32_t)((warpN * 32 + (lane & 15)) * 128);

    for (int c = 0; c < 16; ++c) {
        if (c < 15) {
            const uint32_t st2 = sb + (uint32_t)((c + 1) & 1) * 65536u;
            const int k0 = (c + 1) << 6;
            load_tile(st2 + 0u,      Ahp, m0, k0, tid);
            load_tile(st2 + 16384u,  Alp, m0, k0, tid);
            load_tile(st2 + 32768u,  Bhp, n0, k0, tid);
            load_tile(st2 + 49152u,  Blp, n0, k0, tid);
            asm volatile("cp.async.commit_group;");
            asm volatile("cp.async.wait_group 1;");   // chunk c resident
        } else {
            asm volatile("cp.async.wait_group 0;");
        }
        __syncthreads();

        const uint32_t st = sb + (uint32_t)(c & 1) * 65536u;
#pragma unroll
        for (int kk = 0; kk < 4; ++kk) {
            const uint32_t cs = ((uint32_t)(kk * 32) + halfoff) ^ rmask;

            uint32_t ah[4][4], al[4][4];
#pragma unroll
            for (int mi = 0; mi < 4; ++mi) {
                ldsm4(ah[mi], st + baseA + (uint32_t)(mi * 2048) + cs);
                ldsm4(al[mi], st + 16384u + baseA + (uint32_t)(mi * 2048) + cs);
            }
            uint32_t bh[4][2], bl[4][2];
#pragma unroll
            for (int nb = 0; nb < 2; ++nb) {
                uint32_t r[4];
                ldsm4(r, st + 32768u + baseB + (uint32_t)(nb * 2048) + cs);
                bh[2*nb][0] = r[0]; bh[2*nb+1][0] = r[1];
                bh[2*nb][1] = r[2]; bh[2*nb+1][1] = r[3];
                ldsm4(r, st + 49152u + baseB + (uint32_t)(nb * 2048) + cs);
                bl[2*nb][0] = r[0]; bl[2*nb+1][0] = r[1];
                bl[2*nb][1] = r[2]; bl[2*nb+1][1] = r[3];
            }
#pragma unroll
            for (int mi = 0; mi < 4; ++mi)
#pragma unroll
                for (int ni = 0; ni < 4; ++ni) {
                    mma_bf16(acc[mi][ni], ah[mi], bh[ni]);   // Ah*Bh
                    mma_bf16(acc[mi][ni], ah[mi], bl[ni]);   // Ah*Bl
                    mma_bf16(acc[mi][ni], al[mi], bh[ni]);   // Al*Bh
                }
        }
        __syncthreads();   // compute done before this stage is overwritten
    }

    // epilogue: c0,c1 -> (row, col..col+1); c2,c3 -> (row+8, col..col+1)
    const int er = lane >> 2;
    const int ec = (lane & 3) * 2;
#pragma unroll
    for (int mi = 0; mi < 4; ++mi) {
        const int row = m0 + warpM * 64 + mi * 16 + er;
#pragma unroll
        for (int ni = 0; ni < 4; ++ni) {
            const int col = n0 + warpN * 32 + ni * 8 + ec;
            const float b0 = bias[col], b1 = bias[col + 1];
            float v0 = acc[mi][ni][0] + b0, v1 = acc[mi][ni][1] + b1;
            float v2 = acc[mi][ni][2] + b0, v3 = acc[mi][ni][3] + b1;
            if (act) {
                v0 = 1.f / (1.f + __expf(-v0)); v1 = 1.f / (1.f + __expf(-v1));
                v2 = 1.f / (1.f + __expf(-v2)); v3 = 1.f / (1.f + __expf(-v3));
            }
            *(float2*)(C + (size_t)row * N + col)       = make_float2(v0, v1);
            *(float2*)(C + (size_t)(row + 8) * N + col) = make_float2(v2, v3);
        }
    }
}

// ---------------- DWARF attention core --------------------------------------
// One warp per (b,h,n); writes hi/lo bf16 split of gated output directly.
__global__ void __launch_bounds__(256) attn_kernel(
    const float* __restrict__ qkv, const float* __restrict__ gate,
    const float* __restrict__ Wqs, const float* __restrict__ sg,
    const float* __restrict__ idb, const float* __restrict__ pb,
    __nv_bfloat16* __restrict__ Gh, __nv_bfloat16* __restrict__ Gl)
{
    const int lane = threadIdx.x & 31;
    const int wid  = (blockIdx.x << 3) + (threadIdx.x >> 5); // 131072 warps
    const int n = wid & 2047;
    const int h = (wid >> 11) & 15;
    const int b = wid >> 15;

    const float2 q2 = *(const float2*)(qkv + ((size_t)(b * 2048 + n)) * 3072 + h * 64 + 2 * lane);

    // gains = softmax_s( q . W_qscale[s] + scale_gain[s,h] )
    float gains[11];
    float mx = -1e30f;
#pragma unroll
    for (int s = 0; s < 11; s++) {
        float2 w = *(const float2*)(Wqs + s * 64 + 2 * lane);
        float p = warp_sum(q2.x * w.x + q2.y * w.y) + sg[s * 16 + h];
        gains[s] = p;
        mx = fmaxf(mx, p);
    }
    float ssum = 0.f;
#pragma unroll
    for (int s = 0; s < 11; s++) { float e = __expf(gains[s] - mx); gains[s] = e; ssum += e; }
    {
        float inv = 1.f / ssum;
#pragma unroll
        for (int s = 0; s < 11; s++) gains[s] *= inv;
    }

    const float* kb = qkv + ((size_t)b * 2048) * 3072 + 1024 + h * 64 + 2 * lane;
    const float* vb = kb + 1024;

    const float D4v[4] = {0.4829629131445341f, 0.8365163037378079f,
                          0.2241438680420134f, -0.1294095225512604f};

    // offset-0: 11 tau=0 taps + identity bypass share dot(q,k[n])
    const float2 k0 = *(const float2*)(kb + (size_t)n * 3072);
    const float2 v0 = *(const float2*)(vb + (size_t)n * 3072);
    const float dot0 = warp_sum(q2.x * k0.x + q2.y * k0.y);

    float ax = 0.f, ay = 0.f, z = 0.f;
#pragma unroll
    for (int j = 0; j < 11; j++) {
        float t = dot0 + pb[(j * 4) * 16 + h];
        float feat = (t > 0.f) ? (t + 1.f) : __expf(t);      // elu(t)+1
        float w = gains[j] * D4v[0] * feat;
        ax = fmaf(w, v0.x, ax); ay = fmaf(w, v0.y, ay); z += w;
    }
    {
        float byp = log1pf(__expf(idb[h]));                  // softplus
        float lf  = (dot0 > 0.f) ? (dot0 + 1.f) : __expf(dot0);
        float w = byp * lf;
        ax = fmaf(w, v0.x, ax); ay = fmaf(w, v0.y, ay); z += w;
    }

    // 21 distinct nonzero offsets (odd index carries two (j,tau) pairs)
    const int OFF[21] = {1,2,3,4,6,8,12,16,24,32,48,64,96,128,192,256,384,512,768,1024,1536};
    const int J1 [21] = {0,0,0,1,1,2,2,3,3,4,4,5,5,6,6,7,7,8,8,9,9};
    const int T1 [21] = {1,2,3,2,3,2,3,2,3,2,3,2,3,2,3,2,3,2,3,2,3};

#pragma unroll
    for (int i = 0; i < 21; i++) {
        const int m = n - OFF[i];
        float dpart = 0.f;
        float2 vm = make_float2(0.f, 0.f);
        if (m >= 0) {   // warp-uniform branch
            float2 km = *(const float2*)(kb + (size_t)m * 3072);
            vm        = *(const float2*)(vb + (size_t)m * 3072);
            dpart = q2.x * km.x + q2.y * km.y;
        }
        const float dot = warp_sum(dpart);

        const int j1 = J1[i], tt = T1[i];
        float t    = dot + pb[(j1 * 4 + tt) * 16 + h];
        float feat = (t > 0.f) ? (t + 1.f) : __expf(t);
        float c1   = D4v[tt];
        float w    = gains[j1] * c1 * feat;
        float zc   = gains[j1] * fabsf(c1) * feat;
        if (i & 1) {
            float t2 = dot + pb[((j1 + 1) * 4 + 1) * 16 + h];
            float f2 = (t2 > 0.f) ? (t2 + 1.f) : __expf(t2);
            float w2 = gains[j1 + 1] * D4v[1] * f2;
            w += w2; zc += w2;
        }
        z += zc;                                             // bias-only when m<0
        if (m >= 0) { ax = fmaf(w, vm.x, ax); ay = fmaf(w, vm.y, ay); }
    }

    // normalize, gate, write hi/lo bf16 split of G
    const float invz = 1.f / (z + 1e-6f);
    const size_t gi = (size_t)(b * 2048 + n) * 1024 + h * 64 + 2 * lane;
    const float2 gt = *(const float2*)(gate + gi);
    float ox = ax * invz * gt.x;
    float oy = ay * invz * gt.y;

    __nv_bfloat16 hx = __float2bfloat16(ox);
    __nv_bfloat16 hy = __float2bfloat16(oy);
    __nv_bfloat162 h2; h2.x = hx; h2.y = hy;
    __nv_bfloat162 l2;
    l2.x = __float2bfloat16(ox - __bfloat162float(hx));
    l2.y = __float2bfloat16(oy - __bfloat162float(hy));
    *(__nv_bfloat162*)(Gh + gi) = h2;
    *(__nv_bfloat162*)(Gl + gi) = l2;
}

// ---------------- launch -----------------------------------------------------
extern "C" void kernel_launch(void* const* d_in, const int* in_sizes, int n_in,
                              void* d_out, int out_size) {
    const float* x    = (const float*)d_in[0];
    const float* Wqkv = (const float*)d_in[1];
    const float* bqkv = (const float*)d_in[2];
    const float* Wout = (const float*)d_in[3];
    const float* bout = (const float*)d_in[4];
    const float* Wg   = (const float*)d_in[5];
    const float* bg   = (const float*)d_in[6];
    const float* sg   = (const float*)d_in[7];
    const float* Wqs  = (const float*)d_in[8];
    const float* idb  = (const float*)d_in[9];
    const float* pb   = (const float*)d_in[10];
    float* out = (float*)d_out;

    float *qkv, *gate;
    __nv_bfloat16 *xh, *xl, *Wqh, *Wql, *Wgh, *Wgl, *Woh, *Wol, *Gh, *Gl;
    cudaGetSymbolAddress((void**)&qkv,  g_qkv);
    cudaGetSymbolAddress((void**)&gate, g_gate);
    cudaGetSymbolAddress((void**)&xh,  g_xh);  cudaGetSymbolAddress((void**)&xl,  g_xl);
    cudaGetSymbolAddress((void**)&Wqh, g_Wqh); cudaGetSymbolAddress((void**)&Wql, g_Wql);
    cudaGetSymbolAddress((void**)&Wgh, g_Wgh); cudaGetSymbolAddress((void**)&Wgl, g_Wgl);
    cudaGetSymbolAddress((void**)&Woh, g_Woh); cudaGetSymbolAddress((void**)&Wol, g_Wol);
    cudaGetSymbolAddress((void**)&Gh,  g_Gh);  cudaGetSymbolAddress((void**)&Gl,  g_Gl);

    cudaFuncSetAttribute(gemm_tc, cudaFuncAttributeMaxDynamicSharedMemorySize, GEMM_SMEM);

    // hi/lo splits
    split_hl<<<(8192 * 1024 / 2) / 256, 256>>>(x,    xh,  xl,  8192 * 1024 / 2);
    split_hl<<<(3072 * 1024 / 2) / 256, 256>>>(Wqkv, Wqh, Wql, 3072 * 1024 / 2);
    split_hl<<<(1024 * 1024 / 2) / 256, 256>>>(Wg,   Wgh, Wgl, 1024 * 1024 / 2);
    split_hl<<<(1024 * 1024 / 2) / 256, 256>>>(Wout, Woh, Wol, 1024 * 1024 / 2);

    // 1) qkv = x @ W_qkv^T + b_qkv            [8192, 3072]
    gemm_tc<<<dim3(3072 / 128, 8192 / 128), 256, GEMM_SMEM>>>(
        xh, xl, Wqh, Wql, bqkv, qkv, 3072, 0);
    // 2) gate = sigmoid(x @ W_gate^T + b_g)   [8192, 1024]
    gemm_tc<<<dim3(1024 / 128, 8192 / 128), 256, GEMM_SMEM>>>(
        xh, xl, Wgh, Wgl, bg, gate, 1024, 1);
    // 3) DWARF attention -> gated G (hi/lo bf16)
    attn_kernel<<<131072 / 8, 256>>>(qkv, gate, Wqs, sg, idb, pb, Gh, Gl);
    // 4) out = G @ W_out^T + b_out            [8192, 1024]
    gemm_tc<<<dim3(1024 / 128, 8192 / 128), 256, GEMM_SMEM>>>(
        Gh, Gl, Woh, Wol, bout, out, 1024, 0);
}

// round 17
// speedup vs baseline: 2.3303x; 1.0106x over previous
#include <cuda_runtime.h>
#include <cuda_bf16.h>
#include <cstdint>

// Problem constants: B=4, N=2048, D=1024, H=16, HD=64, M=B*N=8192, K=1024 everywhere.

// ---------------- scratch (device globals; no allocation allowed) ----------
__device__ float g_qkv [8192u * 3072u];          // qkv projection output (fp32)
__device__ float g_gate[8192u * 1024u];          // sigmoid gate (fp32)
__device__ __nv_bfloat16 g_xh [8192u * 1024u];   // x hi/lo
__device__ __nv_bfloat16 g_xl [8192u * 1024u];
__device__ __nv_bfloat16 g_Wqh[3072u * 1024u];   // W_qkv hi/lo
__device__ __nv_bfloat16 g_Wql[3072u * 1024u];
__device__ __nv_bfloat16 g_Wgh[1024u * 1024u];   // W_gate hi/lo
__device__ __nv_bfloat16 g_Wgl[1024u * 1024u];
__device__ __nv_bfloat16 g_Woh[1024u * 1024u];   // W_out hi/lo
__device__ __nv_bfloat16 g_Wol[1024u * 1024u];
__device__ __nv_bfloat16 g_Gh [8192u * 1024u];   // gated attn output hi/lo
__device__ __nv_bfloat16 g_Gl [8192u * 1024u];

// ---------------- helpers ---------------------------------------------------
__device__ __forceinline__ uint32_t smem_u32(const void* p) {
    return (uint32_t)__cvta_generic_to_shared(p);
}
__device__ __forceinline__ float warp_sum(float v) {
#pragma unroll
    for (int s = 16; s > 0; s >>= 1) v += __shfl_xor_sync(0xffffffffu, v, s);
    return v;
}
__device__ __forceinline__ void ldsm4(uint32_t* r, uint32_t addr) {
    asm volatile("ldmatrix.sync.aligned.m8n8.x4.shared.b16 {%0,%1,%2,%3}, [%4];"
                 : "=r"(r[0]), "=r"(r[1]), "=r"(r[2]), "=r"(r[3]) : "r"(addr));
}
__device__ __forceinline__ void mma_bf16(float* c, const uint32_t* a, const uint32_t* b) {
    asm volatile(
        "mma.sync.aligned.m16n8k16.row.col.f32.bf16.bf16.f32 "
        "{%0,%1,%2,%3}, {%4,%5,%6,%7}, {%8,%9}, {%0,%1,%2,%3};"
        : "+f"(c[0]), "+f"(c[1]), "+f"(c[2]), "+f"(c[3])
        : "r"(a[0]), "r"(a[1]), "r"(a[2]), "r"(a[3]), "r"(b[0]), "r"(b[1]));
}

// ---------------- fp32 -> (hi, lo) bf16 split -------------------------------
__global__ void __launch_bounds__(256) split_hl(
    const float* __restrict__ src, __nv_bfloat16* __restrict__ hi,
    __nv_bfloat16* __restrict__ lo, int n2)
{
    int i = blockIdx.x * 256 + threadIdx.x;
    if (i >= n2) return;
    float2 v = ((const float2*)src)[i];
    __nv_bfloat16 hx = __float2bfloat16(v.x);
    __nv_bfloat16 hy = __float2bfloat16(v.y);
    __nv_bfloat162 h2; h2.x = hx; h2.y = hy;
    __nv_bfloat162 l2;
    l2.x = __float2bfloat16(v.x - __bfloat162float(hx));
    l2.y = __float2bfloat16(v.y - __bfloat162float(hy));
    ((__nv_bfloat162*)hi)[i] = h2;
    ((__nv_bfloat162*)lo)[i] = l2;
}

// ---------------- cp.async loader: 128x64 bf16 tile, SW128 swizzle ----------
// K is fixed at 1024 elements for all GEMMs. 128 rows x 128 bytes per tile.
__device__ __forceinline__ void load_tile(uint32_t dst,
                                          const __nv_bfloat16* __restrict__ g,
                                          int row0, int k0, int tid)
{
    const __nv_bfloat16* base = g + (size_t)row0 * 1024 + k0;
#pragma unroll
    for (int it = 0; it < 4; ++it) {
        int s = tid + it * 256;                  // 1024 x 16B segments
        int r = s >> 3, sc = s & 7;
        uint32_t off = (uint32_t)(r * 128 + sc * 16);
        uint32_t d = dst + (off ^ ((off >> 3) & 0x70u));
        const void* src = base + (size_t)r * 1024 + sc * 8;
        asm volatile("cp.async.cg.shared.global [%0], [%1], 16;" :: "r"(d), "l"(src));
    }
}

// ---------------- HMMA bf16-split NT GEMM -----------------------------------
// C[m,n] = act( sum_k A[m,k]*B[n,k] + bias[n] ), A=Ah+Al, B=Bh+Bl (bf16),
// products Ah*Bh + Ah*Bl + Al*Bh, fp32 register accumulation.
// CTA tile 128x128, BK=64, 8 warps (2x4), warp tile 64x32.
// 3-stage cp.async pipeline, ONE __syncthreads per K-chunk.
#define STAGE_BYTES 65536u
#define GEMM_SMEM   (1024u + 3u * STAGE_BYTES)

__global__ void __launch_bounds__(256, 1) gemm_tc(
    const __nv_bfloat16* __restrict__ Ahp, const __nv_bfloat16* __restrict__ Alp,
    const __nv_bfloat16* __restrict__ Bhp, const __nv_bfloat16* __restrict__ Blp,
    const float* __restrict__ bias, float* __restrict__ C,
    int N, int act)
{
    extern __shared__ char dsm[];
    const int tid  = threadIdx.x;
    const int lane = tid & 31;
    const int wid  = tid >> 5;
    const int warpM = wid >> 2;            // 0..1
    const int warpN = wid & 3;             // 0..3
    const int m0 = blockIdx.y * 128;
    const int n0 = blockIdx.x * 128;
    const uint32_t sb = (smem_u32(dsm) + 1023u) & ~1023u;

    float acc[4][4][4];
#pragma unroll
    for (int a = 0; a < 4; a++)
#pragma unroll
        for (int b = 0; b < 4; b++)
#pragma unroll
            for (int c = 0; c < 4; c++) acc[a][b][c] = 0.f;

    // prologue: stages 0,1 <- chunks 0,1
#pragma unroll
    for (int p = 0; p < 2; ++p) {
        const uint32_t st = sb + (uint32_t)p * STAGE_BYTES;
        load_tile(st + 0u,      Ahp, m0, p << 6, tid);
        load_tile(st + 16384u,  Alp, m0, p << 6, tid);
        load_tile(st + 32768u,  Bhp, n0, p << 6, tid);
        load_tile(st + 49152u,  Blp, n0, p << 6, tid);
        asm volatile("cp.async.commit_group;");
    }

    // ldmatrix addressing: rows have 128B stride; SW128 XOR mask = (row&7)<<4.
    const uint32_t rmask   = (uint32_t)((lane & 7) << 4);
    const uint32_t halfoff = (uint32_t)((lane >> 4) << 4);   // k-half select
    const uint32_t baseA = (uint32_t)((warpM * 64 + (lane & 15)) * 128);
    const uint32_t baseB = (uint32_t)((warpN * 32 + (lane & 15)) * 128);

    int stage = 0, pstage = 2;
    for (int c = 0; c < 16; ++c) {
        // chunk c resident (outstanding at top: {c, c+1})
        if (c < 14) asm volatile("cp.async.wait_group 1;");
        else        asm volatile("cp.async.wait_group 0;");
        __syncthreads();   // compute of c-1 done by ALL warps; chunk c visible

        // prefetch chunk c+2 into stage consumed at iteration c-1
        if (c + 2 < 16) {
            const uint32_t st2 = sb + (uint32_t)pstage * STAGE_BYTES;
            const int k0 = (c + 2) << 6;
            load_tile(st2 + 0u,      Ahp, m0, k0, tid);
            load_tile(st2 + 16384u,  Alp, m0, k0, tid);
            load_tile(st2 + 32768u,  Bhp, n0, k0, tid);
            load_tile(st2 + 49152u,  Blp, n0, k0, tid);
            asm volatile("cp.async.commit_group;");
        }
        if (++pstage == 3) pstage = 0;

        const uint32_t st = sb + (uint32_t)stage * STAGE_BYTES;
        if (++stage == 3) stage = 0;
#pragma unroll
        for (int kk = 0; kk < 4; ++kk) {
            const uint32_t cs = ((uint32_t)(kk * 32) + halfoff) ^ rmask;

            uint32_t ah[4][4], al[4][4];
#pragma unroll
            for (int mi = 0; mi < 4; ++mi) {
                ldsm4(ah[mi], st + baseA + (uint32_t)(mi * 2048) + cs);
                ldsm4(al[mi], st + 16384u + baseA + (uint32_t)(mi * 2048) + cs);
            }
            uint32_t bh[4][2], bl[4][2];
#pragma unroll
            for (int nb = 0; nb < 2; ++nb) {
                uint32_t r[4];
                ldsm4(r, st + 32768u + baseB + (uint32_t)(nb * 2048) + cs);
                bh[2*nb][0] = r[0]; bh[2*nb+1][0] = r[1];
                bh[2*nb][1] = r[2]; bh[2*nb+1][1] = r[3];
                ldsm4(r, st + 49152u + baseB + (uint32_t)(nb * 2048) + cs);
                bl[2*nb][0] = r[0]; bl[2*nb+1][0] = r[1];
                bl[2*nb][1] = r[2]; bl[2*nb+1][1] = r[3];
            }
#pragma unroll
            for (int mi = 0; mi < 4; ++mi)
#pragma unroll
                for (int ni = 0; ni < 4; ++ni) {
                    mma_bf16(acc[mi][ni], ah[mi], bh[ni]);   // Ah*Bh
                    mma_bf16(acc[mi][ni], ah[mi], bl[ni]);   // Ah*Bl
                    mma_bf16(acc[mi][ni], al[mi], bh[ni]);   // Al*Bh
                }
        }
    }

    // epilogue: c0,c1 -> (row, col..col+1); c2,c3 -> (row+8, col..col+1)
    const int er = lane >> 2;
    const int ec = (lane & 3) * 2;
#pragma unroll
    for (int mi = 0; mi < 4; ++mi) {
        const int row = m0 + warpM * 64 + mi * 16 + er;
#pragma unroll
        for (int ni = 0; ni < 4; ++ni) {
            const int col = n0 + warpN * 32 + ni * 8 + ec;
            const float b0 = bias[col], b1 = bias[col + 1];
            float v0 = acc[mi][ni][0] + b0, v1 = acc[mi][ni][1] + b1;
            float v2 = acc[mi][ni][2] + b0, v3 = acc[mi][ni][3] + b1;
            if (act) {
                v0 = 1.f / (1.f + __expf(-v0)); v1 = 1.f / (1.f + __expf(-v1));
                v2 = 1.f / (1.f + __expf(-v2)); v3 = 1.f / (1.f + __expf(-v3));
            }
            *(float2*)(C + (size_t)row * N + col)       = make_float2(v0, v1);
            *(float2*)(C + (size_t)(row + 8) * N + col) = make_float2(v2, v3);
        }
    }
}

// ---------------- DWARF attention core --------------------------------------
// One warp per (b,h,n); writes hi/lo bf16 split of gated output directly.
__global__ void __launch_bounds__(256) attn_kernel(
    const float* __restrict__ qkv, const float* __restrict__ gate,
    const float* __restrict__ Wqs, const float* __restrict__ sg,
    const float* __restrict__ idb, const float* __restrict__ pb,
    __nv_bfloat16* __restrict__ Gh, __nv_bfloat16* __restrict__ Gl)
{
    const int lane = threadIdx.x & 31;
    const int wid  = (blockIdx.x << 3) + (threadIdx.x >> 5); // 131072 warps
    const int n = wid & 2047;
    const int h = (wid >> 11) & 15;
    const int b = wid >> 15;

    const float2 q2 = *(const float2*)(qkv + ((size_t)(b * 2048 + n)) * 3072 + h * 64 + 2 * lane);

    // gains = softmax_s( q . W_qscale[s] + scale_gain[s,h] )
    float gains[11];
    float mx = -1e30f;
#pragma unroll
    for (int s = 0; s < 11; s++) {
        float2 w = *(const float2*)(Wqs + s * 64 + 2 * lane);
        float p = warp_sum(q2.x * w.x + q2.y * w.y) + sg[s * 16 + h];
        gains[s] = p;
        mx = fmaxf(mx, p);
    }
    float ssum = 0.f;
#pragma unroll
    for (int s = 0; s < 11; s++) { float e = __expf(gains[s] - mx); gains[s] = e; ssum += e; }
    {
        float inv = 1.f / ssum;
#pragma unroll
        for (int s = 0; s < 11; s++) gains[s] *= inv;
    }

    const float* kb = qkv + ((size_t)b * 2048) * 3072 + 1024 + h * 64 + 2 * lane;
    const float* vb = kb + 1024;

    const float D4v[4] = {0.4829629131445341f, 0.8365163037378079f,
                          0.2241438680420134f, -0.1294095225512604f};

    // offset-0: 11 tau=0 taps + identity bypass share dot(q,k[n])
    const float2 k0 = *(const float2*)(kb + (size_t)n * 3072);
    const float2 v0 = *(const float2*)(vb + (size_t)n * 3072);
    const float dot0 = warp_sum(q2.x * k0.x + q2.y * k0.y);

    float ax = 0.f, ay = 0.f, z = 0.f;
#pragma unroll
    for (int j = 0; j < 11; j++) {
        float t = dot0 + pb[(j * 4) * 16 + h];
        float feat = (t > 0.f) ? (t + 1.f) : __expf(t);      // elu(t)+1
        float w = gains[j] * D4v[0] * feat;
        ax = fmaf(w, v0.x, ax); ay = fmaf(w, v0.y, ay); z += w;
    }
    {
        float byp = log1pf(__expf(idb[h]));                  // softplus
        float lf  = (dot0 > 0.f) ? (dot0 + 1.f) : __expf(dot0);
        float w = byp * lf;
        ax = fmaf(w, v0.x, ax); ay = fmaf(w, v0.y, ay); z += w;
    }

    // 21 distinct nonzero offsets (odd index carries two (j,tau) pairs)
    const int OFF[21] = {1,2,3,4,6,8,12,16,24,32,48,64,96,128,192,256,384,512,768,1024,1536};
    const int J1 [21] = {0,0,0,1,1,2,2,3,3,4,4,5,5,6,6,7,7,8,8,9,9};
    const int T1 [21] = {1,2,3,2,3,2,3,2,3,2,3,2,3,2,3,2,3,2,3,2,3};

#pragma unroll
    for (int i = 0; i < 21; i++) {
        const int m = n - OFF[i];
        float dpart = 0.f;
        float2 vm = make_float2(0.f, 0.f);
        if (m >= 0) {   // warp-uniform branch
            float2 km = *(const float2*)(kb + (size_t)m * 3072);
            vm        = *(const float2*)(vb + (size_t)m * 3072);
            dpart = q2.x * km.x + q2.y * km.y;
        }
        const float dot = warp_sum(dpart);

        const int j1 = J1[i], tt = T1[i];
        float t    = dot + pb[(j1 * 4 + tt) * 16 + h];
        float feat = (t > 0.f) ? (t + 1.f) : __expf(t);
        float c1   = D4v[tt];
        float w    = gains[j1] * c1 * feat;
        float zc   = gains[j1] * fabsf(c1) * feat;
        if (i & 1) {
            float t2 = dot + pb[((j1 + 1) * 4 + 1) * 16 + h];
            float f2 = (t2 > 0.f) ? (t2 + 1.f) : __expf(t2);
            float w2 = gains[j1 + 1] * D4v[1] * f2;
            w += w2; zc += w2;
        }
        z += zc;                                             // bias-only when m<0
        if (m >= 0) { ax = fmaf(w, vm.x, ax); ay = fmaf(w, vm.y, ay); }
    }

    // normalize, gate, write hi/lo bf16 split of G
    const float invz = 1.f / (z + 1e-6f);
    const size_t gi = (size_t)(b * 2048 + n) * 1024 + h * 64 + 2 * lane;
    const float2 gt = *(const float2*)(gate + gi);
    float ox = ax * invz * gt.x;
    float oy = ay * invz * gt.y;

    __nv_bfloat16 hx = __float2bfloat16(ox);
    __nv_bfloat16 hy = __float2bfloat16(oy);
    __nv_bfloat162 h2; h2.x = hx; h2.y = hy;
    __nv_bfloat162 l2;
    l2.x = __float2bfloat16(ox - __bfloat162float(hx));
    l2.y = __float2bfloat16(oy - __bfloat162float(hy));
    *(__nv_bfloat162*)(Gh + gi) = h2;
    *(__nv_bfloat162*)(Gl + gi) = l2;
}

// ---------------- launch -----------------------------------------------------
extern "C" void kernel_launch(void* const* d_in, const int* in_sizes, int n_in,
                              void* d_out, int out_size) {
    const float* x    = (const float*)d_in[0];
    const float* Wqkv = (const float*)d_in[1];
    const float* bqkv = (const float*)d_in[2];
    const float* Wout = (const float*)d_in[3];
    const float* bout = (const float*)d_in[4];
    const float* Wg   = (const float*)d_in[5];
    const float* bg   = (const float*)d_in[6];
    const float* sg   = (const float*)d_in[7];
    const float* Wqs  = (const float*)d_in[8];
    const float* idb  = (const float*)d_in[9];
    const float* pb   = (const float*)d_in[10];
    float* out = (float*)d_out;

    float *qkv, *gate;
    __nv_bfloat16 *xh, *xl, *Wqh, *Wql, *Wgh, *Wgl, *Woh, *Wol, *Gh, *Gl;
    cudaGetSymbolAddress((void**)&qkv,  g_qkv);
    cudaGetSymbolAddress((void**)&gate, g_gate);
    cudaGetSymbolAddress((void**)&xh,  g_xh);  cudaGetSymbolAddress((void**)&xl,  g_xl);
    cudaGetSymbolAddress((void**)&Wqh, g_Wqh); cudaGetSymbolAddress((void**)&Wql, g_Wql);
    cudaGetSymbolAddress((void**)&Wgh, g_Wgh); cudaGetSymbolAddress((void**)&Wgl, g_Wgl);
    cudaGetSymbolAddress((void**)&Woh, g_Woh); cudaGetSymbolAddress((void**)&Wol, g_Wol);
    cudaGetSymbolAddress((void**)&Gh,  g_Gh);  cudaGetSymbolAddress((void**)&Gl,  g_Gl);

    cudaFuncSetAttribute(gemm_tc, cudaFuncAttributeMaxDynamicSharedMemorySize, GEMM_SMEM);

    // hi/lo splits
    split_hl<<<(8192 * 1024 / 2) / 256, 256>>>(x,    xh,  xl,  8192 * 1024 / 2);
    split_hl<<<(3072 * 1024 / 2) / 256, 256>>>(Wqkv, Wqh, Wql, 3072 * 1024 / 2);
    split_hl<<<(1024 * 1024 / 2) / 256, 256>>>(Wg,   Wgh, Wgl, 1024 * 1024 / 2);
    split_hl<<<(1024 * 1024 / 2) / 256, 256>>>(Wout, Woh, Wol, 1024 * 1024 / 2);

    // 1) qkv = x @ W_qkv^T + b_qkv            [8192, 3072]
    gemm_tc<<<dim3(3072 / 128, 8192 / 128), 256, GEMM_SMEM>>>(
        xh, xl, Wqh, Wql, bqkv, qkv, 3072, 0);
    // 2) gate = sigmoid(x @ W_gate^T + b_g)   [8192, 1024]
    gemm_tc<<<dim3(1024 / 128, 8192 / 128), 256, GEMM_SMEM>>>(
        xh, xl, Wgh, Wgl, bg, gate, 1024, 1);
    // 3) DWARF attention -> gated G (hi/lo bf16)
    attn_kernel<<<131072 / 8, 256>>>(qkv, gate, Wqs, sg, idb, pb, Gh, Gl);
    // 4) out = G @ W_out^T + b_out            [8192, 1024]
    gemm_tc<<<dim3(1024 / 128, 8192 / 128), 256, GEMM_SMEM>>>(
        Gh, Gl, Woh, Wol, bout, out, 1024, 0);
}